// round 1
// baseline (speedup 1.0000x reference)
#include <cuda_runtime.h>
#include <cuda_bf16.h>
#include <math.h>

// ---------------------------------------------------------------------------
// Fixed problem shape (from reference setup_inputs)
// ---------------------------------------------------------------------------
#define D_MODEL 1024
#define HEADS   16
#define HEAD_DIM 64
#define FF_DIM  4096
#define SEQ_L   2048
#define EPS     1e-5f
#define MROWS   4096      // B * L = 2 * 2048

// ---------------------------------------------------------------------------
// Scratch (static device globals; no runtime allocation allowed)
// ---------------------------------------------------------------------------
__device__ float g_q   [MROWS * D_MODEL];
__device__ float g_k   [MROWS * D_MODEL];
__device__ float g_v   [MROWS * D_MODEL];
__device__ float g_attn[MROWS * D_MODEL];
__device__ float g_proj[MROWS * D_MODEL];
__device__ float g_h   [MROWS * D_MODEL];
__device__ float g_ff  [MROWS * FF_DIM];
__device__ float g_tmp [MROWS * D_MODEL];

// ---------------------------------------------------------------------------
// SGEMM: C[M,N] = A[M,K] @ B[K,N] + bias[N]  (optional ReLU)
// 128x128 block tile, BK=8, 256 threads, 8x8 microtile per thread.
// All dims are multiples of 128 / 8 here, so no bounds checks.
// ---------------------------------------------------------------------------
#define GBM 128
#define GBN 128
#define GBK 8

__global__ __launch_bounds__(256) void sgemm_kernel(
    const float* __restrict__ A, const float* __restrict__ B,
    const float* __restrict__ bias, float* __restrict__ C,
    int M, int N, int K, int relu)
{
    __shared__ float As[GBK][GBM];
    __shared__ float Bs[GBK][GBN];

    const int tid = threadIdx.x;
    const int row0 = blockIdx.y * GBM;
    const int col0 = blockIdx.x * GBN;

    // global loads: 1 float4 of A and 1 float4 of B per thread per K-step
    const int a_row = tid >> 1;           // 0..127
    const int a_col = (tid & 1) * 4;      // 0 or 4
    const int b_row = tid >> 5;           // 0..7
    const int b_col = (tid & 31) * 4;     // 0..124

    const int tx = tid & 15;              // 0..15 -> cols tx*8
    const int ty = tid >> 4;              // 0..15 -> rows ty*8

    const float* Aptr = A + (size_t)(row0 + a_row) * K + a_col;
    const float* Bptr = B + (size_t)b_row * N + col0 + b_col;

    float acc[8][8];
#pragma unroll
    for (int i = 0; i < 8; i++)
#pragma unroll
        for (int j = 0; j < 8; j++) acc[i][j] = 0.f;

    for (int k0 = 0; k0 < K; k0 += GBK) {
        float4 av = *(const float4*)(Aptr + k0);
        float4 bv = *(const float4*)(Bptr + (size_t)k0 * N);
        __syncthreads();
        As[a_col + 0][a_row] = av.x;
        As[a_col + 1][a_row] = av.y;
        As[a_col + 2][a_row] = av.z;
        As[a_col + 3][a_row] = av.w;
        *(float4*)&Bs[b_row][b_col] = bv;
        __syncthreads();

#pragma unroll
        for (int kk = 0; kk < GBK; kk++) {
            float a[8], b[8];
            *(float4*)&a[0] = *(const float4*)&As[kk][ty * 8 + 0];
            *(float4*)&a[4] = *(const float4*)&As[kk][ty * 8 + 4];
            *(float4*)&b[0] = *(const float4*)&Bs[kk][tx * 8 + 0];
            *(float4*)&b[4] = *(const float4*)&Bs[kk][tx * 8 + 4];
#pragma unroll
            for (int i = 0; i < 8; i++)
#pragma unroll
                for (int j = 0; j < 8; j++)
                    acc[i][j] = fmaf(a[i], b[j], acc[i][j]);
        }
    }

    // epilogue: bias (+ReLU), store
    float bb[8];
#pragma unroll
    for (int j = 0; j < 8; j++) bb[j] = bias[col0 + tx * 8 + j];

#pragma unroll
    for (int i = 0; i < 8; i++) {
        float* cp = C + (size_t)(row0 + ty * 8 + i) * N + col0 + tx * 8;
        float out[8];
#pragma unroll
        for (int j = 0; j < 8; j++) {
            float vv = acc[i][j] + bb[j];
            out[j] = relu ? fmaxf(vv, 0.f) : vv;
        }
        *(float4*)&cp[0] = *(float4*)&out[0];
        *(float4*)&cp[4] = *(float4*)&out[4];
    }
}

// ---------------------------------------------------------------------------
// Flash-attention (fp32, non-causal). One block = (b,h, 64 query rows).
// smem: Qt[64][64] (d-major), KP[64][64] (K^T, later reused for P^T),
//       Vs[64][64]. Exactly 48 KB.
// Thread layout: 256 threads, (tr,tc) each owns 4 rows x 4 cols.
// ---------------------------------------------------------------------------
__global__ __launch_bounds__(256) void attn_kernel(
    const float* __restrict__ q, const float* __restrict__ k,
    const float* __restrict__ v, float* __restrict__ o, int L)
{
    __shared__ float Qt[64][64];   // [d][row]
    __shared__ float KP[64][64];   // K^T: [d][key]  ->  P^T: [key][row]
    __shared__ float Vs[64][64];   // [key][d]

    const int bh = blockIdx.y;
    const int b  = bh / HEADS;
    const int h  = bh % HEADS;
    const int l0 = blockIdx.x * 64;
    const int tid = threadIdx.x;
    const int tr = tid >> 4, tc = tid & 15;
    const int r0 = tr * 4, c0 = tc * 4;

    const size_t base = ((size_t)b * L) * D_MODEL + h * HEAD_DIM;

    // load Q tile (transposed into Qt)
    for (int i = tid; i < 64 * 16; i += 256) {
        int rr = i >> 4;
        int cc = (i & 15) * 4;
        float4 qv = *(const float4*)(q + base + (size_t)(l0 + rr) * D_MODEL + cc);
        Qt[cc + 0][rr] = qv.x; Qt[cc + 1][rr] = qv.y;
        Qt[cc + 2][rr] = qv.z; Qt[cc + 3][rr] = qv.w;
    }

    float m_i[4], l_i[4], acc[4][4];
#pragma unroll
    for (int i = 0; i < 4; i++) {
        m_i[i] = -3.0e38f; l_i[i] = 0.f;
#pragma unroll
        for (int j = 0; j < 4; j++) acc[i][j] = 0.f;
    }

    for (int s0 = 0; s0 < L; s0 += 64) {
        __syncthreads();   // previous-iteration smem reads done
        for (int i = tid; i < 64 * 16; i += 256) {
            int rr = i >> 4;
            int cc = (i & 15) * 4;
            float4 kv = *(const float4*)(k + base + (size_t)(s0 + rr) * D_MODEL + cc);
            KP[cc + 0][rr] = kv.x; KP[cc + 1][rr] = kv.y;
            KP[cc + 2][rr] = kv.z; KP[cc + 3][rr] = kv.w;
            float4 vv = *(const float4*)(v + base + (size_t)(s0 + rr) * D_MODEL + cc);
            *(float4*)&Vs[rr][cc] = vv;
        }
        __syncthreads();

        // S = Q @ K^T  (4x4 per thread)
        float s[4][4];
#pragma unroll
        for (int i = 0; i < 4; i++)
#pragma unroll
            for (int j = 0; j < 4; j++) s[i][j] = 0.f;
        for (int kk = 0; kk < 64; kk++) {
            float4 qv = *(const float4*)&Qt[kk][r0];
            float4 kv = *(const float4*)&KP[kk][c0];
            float qa[4] = {qv.x, qv.y, qv.z, qv.w};
            float ka[4] = {kv.x, kv.y, kv.z, kv.w};
#pragma unroll
            for (int i = 0; i < 4; i++)
#pragma unroll
                for (int j = 0; j < 4; j++)
                    s[i][j] = fmaf(qa[i], ka[j], s[i][j]);
        }

        // online softmax update (scale = 1/sqrt(64) = 0.125)
        float p[4][4];
#pragma unroll
        for (int i = 0; i < 4; i++) {
            float tmax = -3.0e38f;
#pragma unroll
            for (int j = 0; j < 4; j++) {
                s[i][j] *= 0.125f;
                tmax = fmaxf(tmax, s[i][j]);
            }
#pragma unroll
            for (int off = 1; off < 16; off <<= 1)
                tmax = fmaxf(tmax, __shfl_xor_sync(0xffffffffu, tmax, off));
            float mnew = fmaxf(m_i[i], tmax);
            float corr = __expf(m_i[i] - mnew);
            l_i[i] *= corr;
#pragma unroll
            for (int j = 0; j < 4; j++) acc[i][j] *= corr;
            float rs = 0.f;
#pragma unroll
            for (int j = 0; j < 4; j++) {
                p[i][j] = __expf(s[i][j] - mnew);
                rs += p[i][j];
            }
#pragma unroll
            for (int off = 1; off < 16; off <<= 1)
                rs += __shfl_xor_sync(0xffffffffu, rs, off);
            l_i[i] += rs;
            m_i[i] = mnew;
        }

        __syncthreads();   // done reading KP as K^T
        // store P^T into KP: KP[key][row]
#pragma unroll
        for (int i = 0; i < 4; i++)
#pragma unroll
            for (int j = 0; j < 4; j++)
                KP[c0 + j][r0 + i] = p[i][j];
        __syncthreads();

        // acc += P @ V
        for (int ss = 0; ss < 64; ss++) {
            float4 pv = *(const float4*)&KP[ss][r0];
            float4 vv = *(const float4*)&Vs[ss][c0];
            float pa[4] = {pv.x, pv.y, pv.z, pv.w};
            float va[4] = {vv.x, vv.y, vv.z, vv.w};
#pragma unroll
            for (int i = 0; i < 4; i++)
#pragma unroll
                for (int j = 0; j < 4; j++)
                    acc[i][j] = fmaf(pa[i], va[j], acc[i][j]);
        }
    }

    // write O = acc / l
#pragma unroll
    for (int i = 0; i < 4; i++) {
        float inv = 1.f / l_i[i];
#pragma unroll
        for (int j = 0; j < 4; j++)
            o[base + (size_t)(l0 + r0 + i) * D_MODEL + c0 + j] = acc[i][j] * inv;
    }
}

// ---------------------------------------------------------------------------
// Fused residual + LayerNorm: out = LN(a + r) * g + beta.  One block per row.
// 256 threads x 4 elems = 1024 cols.
// ---------------------------------------------------------------------------
__global__ __launch_bounds__(256) void ln_residual_kernel(
    const float* __restrict__ a, const float* __restrict__ r,
    const float* __restrict__ g, const float* __restrict__ beta,
    float* __restrict__ out)
{
    __shared__ float red[8];
    const int row = blockIdx.x;
    const int tid = threadIdx.x;
    const int lane = tid & 31, warp = tid >> 5;
    const size_t off = (size_t)row * D_MODEL + tid * 4;

    float4 va = *(const float4*)(a + off);
    float4 vr = *(const float4*)(r + off);
    float x[4] = {va.x + vr.x, va.y + vr.y, va.z + vr.z, va.w + vr.w};

    float sum = x[0] + x[1] + x[2] + x[3];
#pragma unroll
    for (int o = 16; o; o >>= 1) sum += __shfl_down_sync(0xffffffffu, sum, o);
    if (lane == 0) red[warp] = sum;
    __syncthreads();
    if (warp == 0) {
        float v = (lane < 8) ? red[lane] : 0.f;
#pragma unroll
        for (int o = 4; o; o >>= 1) v += __shfl_down_sync(0xffu, v, o);
        if (lane == 0) red[0] = v;
    }
    __syncthreads();
    const float mu = red[0] * (1.f / D_MODEL);
    __syncthreads();

    float sq = 0.f;
#pragma unroll
    for (int i = 0; i < 4; i++) {
        float d = x[i] - mu;
        sq += d * d;
    }
#pragma unroll
    for (int o = 16; o; o >>= 1) sq += __shfl_down_sync(0xffffffffu, sq, o);
    if (lane == 0) red[warp] = sq;
    __syncthreads();
    if (warp == 0) {
        float v = (lane < 8) ? red[lane] : 0.f;
#pragma unroll
        for (int o = 4; o; o >>= 1) v += __shfl_down_sync(0xffu, v, o);
        if (lane == 0) red[0] = v;
    }
    __syncthreads();
    const float rstd = rsqrtf(red[0] * (1.f / D_MODEL) + EPS);

    float4 gg = *(const float4*)(g + tid * 4);
    float4 bb = *(const float4*)(beta + tid * 4);
    float ga[4] = {gg.x, gg.y, gg.z, gg.w};
    float ba[4] = {bb.x, bb.y, bb.z, bb.w};
    float y[4];
#pragma unroll
    for (int i = 0; i < 4; i++)
        y[i] = (x[i] - mu) * rstd * ga[i] + ba[i];
    *(float4*)(out + off) = *(float4*)&y[0];
}

// ---------------------------------------------------------------------------
// Launch sequence
// ---------------------------------------------------------------------------
extern "C" void kernel_launch(void* const* d_in, const int* in_sizes, int n_in,
                              void* d_out, int out_size)
{
    const float* x  = (const float*)d_in[0];
    const float* Wq = (const float*)d_in[1];
    const float* bq = (const float*)d_in[2];
    const float* Wk = (const float*)d_in[3];
    const float* bk = (const float*)d_in[4];
    const float* Wv = (const float*)d_in[5];
    const float* bv = (const float*)d_in[6];
    const float* Wm = (const float*)d_in[7];
    const float* bm = (const float*)d_in[8];
    const float* W1 = (const float*)d_in[9];
    const float* b1 = (const float*)d_in[10];
    const float* W2 = (const float*)d_in[11];
    const float* b2 = (const float*)d_in[12];
    const float* g1  = (const float*)d_in[13];
    const float* be1 = (const float*)d_in[14];
    const float* g2  = (const float*)d_in[15];
    const float* be2 = (const float*)d_in[16];
    float* out = (float*)d_out;

    const int M = in_sizes[0] / D_MODEL;   // 4096
    const int L = SEQ_L;
    const int B = M / L;

    float *q, *k, *v, *attn, *proj, *h, *ff, *tmp;
    cudaGetSymbolAddress((void**)&q,    g_q);
    cudaGetSymbolAddress((void**)&k,    g_k);
    cudaGetSymbolAddress((void**)&v,    g_v);
    cudaGetSymbolAddress((void**)&attn, g_attn);
    cudaGetSymbolAddress((void**)&proj, g_proj);
    cudaGetSymbolAddress((void**)&h,    g_h);
    cudaGetSymbolAddress((void**)&ff,   g_ff);
    cudaGetSymbolAddress((void**)&tmp,  g_tmp);

    dim3 blk(256);
    dim3 grid_d(D_MODEL / GBN, M / GBM);   // (8, 32)
    dim3 grid_f(FF_DIM / GBN,  M / GBM);   // (32, 32)

    // QKV projections
    sgemm_kernel<<<grid_d, blk>>>(x, Wq, bq, q, M, D_MODEL, D_MODEL, 0);
    sgemm_kernel<<<grid_d, blk>>>(x, Wk, bk, k, M, D_MODEL, D_MODEL, 0);
    sgemm_kernel<<<grid_d, blk>>>(x, Wv, bv, v, M, D_MODEL, D_MODEL, 0);

    // attention
    dim3 agrid(L / 64, B * HEADS);         // (32, 32)
    attn_kernel<<<agrid, blk>>>(q, k, v, attn, L);

    // output projection + residual LN
    sgemm_kernel<<<grid_d, blk>>>(attn, Wm, bm, proj, M, D_MODEL, D_MODEL, 0);
    ln_residual_kernel<<<M, blk>>>(x, proj, g1, be1, h);

    // FFN
    sgemm_kernel<<<grid_f, blk>>>(h, W1, b1, ff, M, FF_DIM, D_MODEL, 1);
    sgemm_kernel<<<grid_d, blk>>>(ff, W2, b2, tmp, M, D_MODEL, FF_DIM, 0);
    ln_residual_kernel<<<M, blk>>>(h, tmp, g2, be2, out);
}